// round 10
// baseline (speedup 1.0000x reference)
#include <cuda_runtime.h>
#include <math.h>

#define NH 12
#define NB 4
#define SEQ 1024
#define CH 768
#define HD 64
#define BHD 48   // NB*NH
#define QKVLD 2304
#define LOG2E 1.4426950408889634f

// -------- scratch (no allocs allowed) --------
__device__ float g_qkv[NB * SEQ * 3 * CH];   // (4096, 2304)
__device__ float g_relh[BHD * SEQ * 32];
__device__ float g_relw[BHD * SEQ * 32];
__device__ float g_attn[NB * SEQ * CH];      // (4096, 768)

__device__ __forceinline__ unsigned f2tf(float f) {
    unsigned u; asm("cvt.rna.tf32.f32 %0, %1;" : "=r"(u) : "f"(f)); return u;
}
__device__ __forceinline__ float ex2(float x) {
    float y; asm("ex2.approx.ftz.f32 %0, %1;" : "=f"(y) : "f"(x)); return y;
}

// D += A*B, m16n8k8 tf32. a: {(g,t),(g+8,t),(g,t+4),(g+8,t+4)}  b: {(t,g),(t+4,g)}
// c: {(g,2t),(g,2t+1),(g+8,2t),(g+8,2t+1)}
__device__ __forceinline__ void mma_tf32(float* d, const unsigned* a, const unsigned* b) {
    asm volatile(
        "mma.sync.aligned.m16n8k8.row.col.f32.tf32.tf32.f32 "
        "{%0,%1,%2,%3}, {%4,%5,%6,%7}, {%8,%9}, {%0,%1,%2,%3};\n"
        : "+f"(d[0]), "+f"(d[1]), "+f"(d[2]), "+f"(d[3])
        : "r"(a[0]), "r"(a[1]), "r"(a[2]), "r"(a[3]), "r"(b[0]), "r"(b[1]));
}

// ============================================================
// TF32 GEMM: C[M,N] = A[M,K] @ B[K,N] (+bias).
// Block 128x128, BK=32, 256 threads, 8 warps (2m x 4n), warp tile 64x32.
// 2-stage smem double-buffer, one __syncthreads per k-chunk,
// LDG prefetch distance 2. Dynamic smem 74.75 KB, 2 blocks/SM.
// ============================================================
#define GLDA 40
#define GLDB 132
#define G_ASZ (128 * GLDA)
#define G_BSZ (32 * GLDB)
#define GEMM_SMEM ((2 * (G_ASZ + G_BSZ)) * 4)

template <bool BIAS>
__global__ __launch_bounds__(256, 2) void gemm_tf32(
    const float* __restrict__ A, const float* __restrict__ B,
    const float* __restrict__ bias, float* __restrict__ Cm,
    int M, int N, int K) {
    extern __shared__ unsigned gsm[];

    int tid = threadIdx.x;
    int lane = tid & 31, w = tid >> 5;
    int g = lane >> 2, t4 = lane & 3;
    int wm = (w & 1) * 64, wn = (w >> 1) * 32;
    int bm = blockIdx.y * 128, bn = blockIdx.x * 128;

    const int a_r = tid >> 3, a_k = (tid & 7) * 4;     // A: 32 rows x 8 float4 (x4 ii)
    const int a_c = a_k >> 3, a_e = (a_k >> 2) & 1;
    const int b_r = tid >> 5, b_c = (tid & 31) * 4;    // B: 8 rows (x4 ii) x 32 float4

    float acc[4][4][4];
#pragma unroll
    for (int i = 0; i < 4; i++)
#pragma unroll
        for (int j = 0; j < 4; j++)
#pragma unroll
            for (int r = 0; r < 4; r++) acc[i][j][r] = 0.f;

    float4 areg[4], breg[4];

    auto loadg = [&](int k0) {
#pragma unroll
        for (int ii = 0; ii < 4; ii++) {
            areg[ii] = *(const float4*)&A[(size_t)(bm + a_r + 32 * ii) * K + k0 + a_k];
            breg[ii] = *(const float4*)&B[(size_t)(k0 + b_r + 8 * ii) * N + bn + b_c];
        }
    };
    auto stores = [&](int s) {
        unsigned* As2 = gsm + s * G_ASZ;
        unsigned* Bs = gsm + 2 * G_ASZ + s * G_BSZ;
#pragma unroll
        for (int ii = 0; ii < 4; ii++) {
            unsigned* ad = &As2[(a_r + 32 * ii) * GLDA + 8 * a_c + a_e];
            ad[0] = f2tf(areg[ii].x);
            ad[2] = f2tf(areg[ii].y);
            ad[4] = f2tf(areg[ii].z);
            ad[6] = f2tf(areg[ii].w);
            uint4 bv;
            bv.x = f2tf(breg[ii].x); bv.y = f2tf(breg[ii].y);
            bv.z = f2tf(breg[ii].z); bv.w = f2tf(breg[ii].w);
            *(uint4*)&Bs[(b_r + 8 * ii) * GLDB + b_c] = bv;
        }
    };

    const int KC = K >> 5;
    loadg(0);
    stores(0);
    loadg(32);
    __syncthreads();

    for (int kc = 0; kc < KC; kc++) {
        int cur = kc & 1;
        if (kc + 1 < KC) stores(cur ^ 1);
        if (kc + 2 < KC) loadg((kc + 2) * 32);

        const unsigned* Ac = gsm + cur * G_ASZ;
        const unsigned* Bc = gsm + 2 * G_ASZ + cur * G_BSZ;
#pragma unroll
        for (int c = 0; c < 4; c++) {
            unsigned af[4][4], bf[4][2];
#pragma unroll
            for (int i = 0; i < 4; i++) {
                uint2 lo = *(uint2*)&Ac[(wm + 16 * i + g) * GLDA + 8 * c + 2 * t4];
                uint2 hi = *(uint2*)&Ac[(wm + 16 * i + g + 8) * GLDA + 8 * c + 2 * t4];
                af[i][0] = lo.x; af[i][1] = hi.x; af[i][2] = lo.y; af[i][3] = hi.y;
            }
#pragma unroll
            for (int j = 0; j < 4; j++) {
                bf[j][0] = Bc[(c * 8 + t4) * GLDB + wn + 8 * j + g];
                bf[j][1] = Bc[(c * 8 + t4 + 4) * GLDB + wn + 8 * j + g];
            }
#pragma unroll
            for (int i = 0; i < 4; i++)
#pragma unroll
                for (int j = 0; j < 4; j++)
                    mma_tf32(acc[i][j], af[i], bf[j]);
        }
        __syncthreads();
    }

#pragma unroll
    for (int i = 0; i < 4; i++)
#pragma unroll
        for (int j = 0; j < 4; j++) {
            int row = bm + wm + 16 * i + g;
            int col = bn + wn + 8 * j + 2 * t4;
            float2 v0 = make_float2(acc[i][j][0], acc[i][j][1]);
            float2 v1 = make_float2(acc[i][j][2], acc[i][j][3]);
            if (BIAS) {
                float2 bb = *(const float2*)&bias[col];
                v0.x += bb.x; v0.y += bb.y; v1.x += bb.x; v1.y += bb.y;
            }
            *(float2*)&Cm[(size_t)row * N + col] = v0;
            *(float2*)&Cm[(size_t)(row + 8) * N + col] = v1;
        }
}

// ============================================================
// Relative position bias (unchanged).
// ============================================================
__global__ __launch_bounds__(256) void relpos_kernel(
    const float* __restrict__ rph, const float* __restrict__ rpw) {
    __shared__ float Rh[63 * 68], Rw[63 * 68];
    int tid = threadIdx.x;
    int qc = blockIdx.x, bh = blockIdx.y;

    for (int idx = tid; idx < 63 * 64; idx += 256) {
        int row = idx >> 6, d = idx & 63;
        Rh[row * 68 + d] = rph[idx];
        Rw[row * 68 + d] = rpw[idx];
    }
    __syncthreads();

    int ql = tid >> 1, half = tid & 1;
    int q = qc * 128 + ql;
    int b = bh / NH, head = bh % NH;
    int pc = half ? (q & 31) : (q >> 5);
    const float* qptr = &g_qkv[(size_t)(b * SEQ + q) * QKVLD + head * HD];
    const float* T = half ? Rw : Rh;

    float acc[32];
#pragma unroll
    for (int o = 0; o < 32; o++) acc[o] = 0.f;

    for (int d0 = 0; d0 < 64; d0 += 8) {
        float4 v0 = *(const float4*)&qptr[d0];
        float4 v1 = *(const float4*)&qptr[d0 + 4];
        float qd[8] = {v0.x, v0.y, v0.z, v0.w, v1.x, v1.y, v1.z, v1.w};
#pragma unroll
        for (int dd = 0; dd < 8; dd++) {
            float qv = qd[dd];
            const float* Tp = &T[(pc + 31) * 68 + d0 + dd];
#pragma unroll
            for (int o = 0; o < 32; o++)
                acc[o] = fmaf(qv, Tp[-o * 68], acc[o]);
        }
    }
    float* dst = half ? &g_relw[((size_t)bh * SEQ + q) * 32]
                      : &g_relh[((size_t)bh * SEQ + q) * 32];
#pragma unroll
    for (int o = 0; o < 32; o++) dst[o] = acc[o];
}

// ============================================================
// Flash attention, warp-local softmax. Bq=128, Bk=64, 256 thr, 8 warps.
// 2-stage K/V double-buffer, reg prefetch distance 2, one sync/iter.
// ============================================================
#define BQ 128
#define LDK 72
#define LDV 72
#define LDP 72
#define LDH 33
#define KSTG (64 * LDK)
#define VSTG (64 * LDV)
#define ATTN_SMEM ((2 * KSTG + 2 * VSTG + 8 * 16 * LDP + BQ * LDH) * 4)

__global__ __launch_bounds__(256, 1) void attn_mma() {
    extern __shared__ unsigned smu[];
    unsigned* Ks2 = smu;                    // 2 x [64][LDK]  n-major, perm(k)
    unsigned* Vs  = Ks2 + 2 * KSTG;         // 2 x [64][LDV]  key-major, d cols
    unsigned* Pw  = Vs + 2 * VSTG;          // 8 x [16][LDP] per-warp, perm(k)
    float* Bhs    = (float*)(Pw + 8 * 16 * LDP);  // [BQ][LDH] relh * log2e

    int tid = threadIdx.x;
    int lane = tid & 31, w = tid >> 5;
    int g = lane >> 2, t4 = lane & 3;

    int bh = blockIdx.y, qbase = blockIdx.x * BQ;
    int b = bh / NH, head = bh % NH;
    const float* base = &g_qkv[(size_t)b * SEQ * QKVLD + head * HD];

    // stage relh (scaled to log2 domain)
    {
        const float* gh = &g_relh[((size_t)bh * SEQ + qbase) * 32];
        for (int idx = tid; idx < BQ * 32; idx += 256) {
            int r = idx >> 5, c = idx & 31;
            Bhs[r * LDH + c] = LOG2E * gh[r * 32 + c];
        }
    }

    int qr0 = w * 16 + g;      // local q row (a0/a2)
    int qr1 = qr0 + 8;         // (a1/a3)

    // Q fragments (resident all iterations)
    unsigned qa[8][4];
    {
        const float* qp0 = base + (size_t)(qbase + qr0) * QKVLD;
        const float* qp1 = base + (size_t)(qbase + qr1) * QKVLD;
#pragma unroll
        for (int c = 0; c < 8; c++) {
            qa[c][0] = f2tf(qp0[8 * c + t4]);
            qa[c][1] = f2tf(qp1[8 * c + t4]);
            qa[c][2] = f2tf(qp0[8 * c + t4 + 4]);
            qa[c][3] = f2tf(qp1[8 * c + t4 + 4]);
        }
    }
    // relw registers, log2 domain
    float rw0[8], rw1[8];
    {
        const float* p0 = &g_relw[((size_t)bh * SEQ + qbase + qr0) * 32];
        const float* p1 = &g_relw[((size_t)bh * SEQ + qbase + qr1) * 32];
#pragma unroll
        for (int m = 0; m < 4; m++) {
            rw0[2 * m]     = LOG2E * p0[8 * m + 2 * t4];
            rw0[2 * m + 1] = LOG2E * p0[8 * m + 2 * t4 + 1];
            rw1[2 * m]     = LOG2E * p1[8 * m + 2 * t4];
            rw1[2 * m + 1] = LOG2E * p1[8 * m + 2 * t4 + 1];
        }
    }

    float m0 = -1e30f, m1 = -1e30f, l0 = 0.f, l1 = 0.f;
    float oacc[8][4];
#pragma unroll
    for (int nb = 0; nb < 8; nb++)
#pragma unroll
        for (int r = 0; r < 4; r++) oacc[nb][r] = 0.f;

    const int r_ = tid >> 4, d4 = (tid & 15) * 4;
    const int cc_ = d4 >> 3, ee_ = (d4 >> 2) & 1;
    const int i0 = 2 * ((2 * t4) & 3) + ((2 * t4) >> 2);
    const int i1 = 2 * ((2 * t4 + 1) & 3) + ((2 * t4 + 1) >> 2);
    unsigned* Pme = Pw + w * 16 * LDP;
    const float sc = 0.125f * LOG2E;

    // K/V prefetch registers
    float4 kreg[4], vreg[4];
    auto loadKV = [&](int kt) {
#pragma unroll
        for (int ii = 0; ii < 4; ii++) {
            const float* kp = base + (size_t)(kt * 64 + r_ + 16 * ii) * QKVLD + CH + d4;
            kreg[ii] = *(const float4*)kp;
            vreg[ii] = *(const float4*)(kp + CH);
        }
    };
    auto storeKV = [&](int s) {
        unsigned* Kd = Ks2 + s * KSTG;
        unsigned* Vd = Vs + s * VSTG;
#pragma unroll
        for (int ii = 0; ii < 4; ii++) {
            int row = r_ + 16 * ii;
            unsigned* kd = &Kd[row * LDK + 8 * cc_ + ee_];
            kd[0] = f2tf(kreg[ii].x); kd[2] = f2tf(kreg[ii].y);
            kd[4] = f2tf(kreg[ii].z); kd[6] = f2tf(kreg[ii].w);
            uint4 u;
            u.x = f2tf(vreg[ii].x); u.y = f2tf(vreg[ii].y);
            u.z = f2tf(vreg[ii].z); u.w = f2tf(vreg[ii].w);
            *(uint4*)&Vd[row * LDV + d4] = u;
        }
    };

    loadKV(0);
    storeKV(0);
    loadKV(1);
    __syncthreads();

    for (int kt = 0; kt < 16; kt++) {
        int cur = kt & 1;
        if (kt < 15) storeKV(cur ^ 1);
        if (kt < 14) loadKV(kt + 2);

        const unsigned* Kc = Ks2 + cur * KSTG;
        const unsigned* Vc = Vs + cur * VSTG;

        // S = Q K^T over the warp's 16 rows x 64 cols
        float sacc[8][4];
#pragma unroll
        for (int nb = 0; nb < 8; nb++)
#pragma unroll
            for (int r = 0; r < 4; r++) sacc[nb][r] = 0.f;
#pragma unroll
        for (int c = 0; c < 8; c++) {
#pragma unroll
            for (int nb = 0; nb < 8; nb++) {
                uint2 bb2 = *(uint2*)&Kc[(8 * nb + g) * LDK + 8 * c + 2 * t4];
                unsigned bb[2] = {bb2.x, bb2.y};
                mma_tf32(sacc[nb], qa[c], bb);
            }
        }

        // bias + warp-local online softmax (log2 domain)
        float rh0a = Bhs[qr0 * LDH + 2 * kt], rh0b = Bhs[qr0 * LDH + 2 * kt + 1];
        float rh1a = Bhs[qr1 * LDH + 2 * kt], rh1b = Bhs[qr1 * LDH + 2 * kt + 1];
        float mn0 = m0, mn1 = m1;
#pragma unroll
        for (int nb = 0; nb < 8; nb++) {
            float bh0 = nb < 4 ? rh0a : rh0b;
            float bh1 = nb < 4 ? rh1a : rh1b;
            int mi = nb & 3;
            sacc[nb][0] = fmaf(sc, sacc[nb][0], bh0 + rw0[2 * mi]);
            sacc[nb][1] = fmaf(sc, sacc[nb][1], bh0 + rw0[2 * mi + 1]);
            sacc[nb][2] = fmaf(sc, sacc[nb][2], bh1 + rw1[2 * mi]);
            sacc[nb][3] = fmaf(sc, sacc[nb][3], bh1 + rw1[2 * mi + 1]);
            mn0 = fmaxf(mn0, fmaxf(sacc[nb][0], sacc[nb][1]));
            mn1 = fmaxf(mn1, fmaxf(sacc[nb][2], sacc[nb][3]));
        }
        mn0 = fmaxf(mn0, __shfl_xor_sync(0xffffffffu, mn0, 1));
        mn0 = fmaxf(mn0, __shfl_xor_sync(0xffffffffu, mn0, 2));
        mn1 = fmaxf(mn1, __shfl_xor_sync(0xffffffffu, mn1, 1));
        mn1 = fmaxf(mn1, __shfl_xor_sync(0xffffffffu, mn1, 2));
        float cr0 = ex2(m0 - mn0), cr1 = ex2(m1 - mn1);
        m0 = mn0; m1 = mn1;
        float s0 = 0.f, s1 = 0.f;
#pragma unroll
        for (int nb = 0; nb < 8; nb++) {
            float p0 = ex2(sacc[nb][0] - mn0);
            float p1 = ex2(sacc[nb][1] - mn0);
            float p2 = ex2(sacc[nb][2] - mn1);
            float p3 = ex2(sacc[nb][3] - mn1);
            s0 += p0 + p1; s1 += p2 + p3;
            unsigned* pr = &Pme[8 * nb];
            pr[g * LDP + i0] = f2tf(p0);
            pr[g * LDP + i1] = f2tf(p1);
            pr[(g + 8) * LDP + i0] = f2tf(p2);
            pr[(g + 8) * LDP + i1] = f2tf(p3);
        }
        s0 += __shfl_xor_sync(0xffffffffu, s0, 1);
        s0 += __shfl_xor_sync(0xffffffffu, s0, 2);
        s1 += __shfl_xor_sync(0xffffffffu, s1, 1);
        s1 += __shfl_xor_sync(0xffffffffu, s1, 2);
        l0 = l0 * cr0 + s0;
        l1 = l1 * cr1 + s1;
#pragma unroll
        for (int nb = 0; nb < 8; nb++) {
            oacc[nb][0] *= cr0; oacc[nb][1] *= cr0;
            oacc[nb][2] *= cr1; oacc[nb][3] *= cr1;
        }
        __syncwarp();

        // O += P @ V
#pragma unroll
        for (int c = 0; c < 8; c++) {
            uint2 lo = *(uint2*)&Pme[g * LDP + 8 * c + 2 * t4];
            uint2 hi = *(uint2*)&Pme[(g + 8) * LDP + 8 * c + 2 * t4];
            unsigned pa[4] = {lo.x, hi.x, lo.y, hi.y};
            const unsigned* v0 = &Vc[(8 * c + t4) * LDV];
            const unsigned* v1 = &Vc[(8 * c + t4 + 4) * LDV];
#pragma unroll
            for (int nb = 0; nb < 8; nb++) {
                unsigned bb[2] = {v0[8 * nb + g], v1[8 * nb + g]};
                mma_tf32(oacc[nb], pa, bb);
            }
        }
        __syncthreads();
    }

    // normalize + write (B,S,C) layout
    float inv0 = 1.f / l0, inv1 = 1.f / l1;
    float* op0 = &g_attn[(size_t)(b * SEQ + qbase + qr0) * CH + head * HD + 2 * t4];
    float* op1 = &g_attn[(size_t)(b * SEQ + qbase + qr1) * CH + head * HD + 2 * t4];
#pragma unroll
    for (int nb = 0; nb < 8; nb++) {
        *(float2*)&op0[8 * nb] = make_float2(oacc[nb][0] * inv0, oacc[nb][1] * inv0);
        *(float2*)&op1[8 * nb] = make_float2(oacc[nb][2] * inv1, oacc[nb][3] * inv1);
    }
}

// ============================================================
extern "C" void kernel_launch(void* const* d_in, const int* in_sizes, int n_in,
                              void* d_out, int out_size) {
    const float* x     = (const float*)d_in[0];
    const float* Wqkv  = (const float*)d_in[1];
    const float* Wproj = (const float*)d_in[2];
    const float* bproj = (const float*)d_in[3];
    const float* rph   = (const float*)d_in[4];
    const float* rpw   = (const float*)d_in[5];
    float* out = (float*)d_out;

    float* qkv;  cudaGetSymbolAddress((void**)&qkv,  g_qkv);
    float* attn; cudaGetSymbolAddress((void**)&attn, g_attn);

    cudaFuncSetAttribute(gemm_tf32<false>, cudaFuncAttributeMaxDynamicSharedMemorySize, GEMM_SMEM);
    cudaFuncSetAttribute(gemm_tf32<true>, cudaFuncAttributeMaxDynamicSharedMemorySize, GEMM_SMEM);
    cudaFuncSetAttribute(attn_mma, cudaFuncAttributeMaxDynamicSharedMemorySize, ATTN_SMEM);

    // 1) QKV projection: (4096 x 2304) = (4096 x 768) @ (768 x 2304)
    gemm_tf32<false><<<dim3(QKVLD / 128, (NB * SEQ) / 128), 256, GEMM_SMEM>>>(
        x, Wqkv, nullptr, qkv, NB * SEQ, QKVLD, CH);

    // 2) decomposed relative position bias
    relpos_kernel<<<dim3(8, BHD), 256>>>(rph, rpw);

    // 3) attention (tf32 mma, warp-local online softmax, double-buffered)
    attn_mma<<<dim3(SEQ / BQ, BHD), 256, ATTN_SMEM>>>();

    // 4) out projection + bias: (4096 x 768) = (4096 x 768) @ (768 x 768) + b
    gemm_tf32<true><<<dim3(CH / 128, (NB * SEQ) / 128), 256, GEMM_SMEM>>>(
        attn, Wproj, bproj, out, NB * SEQ, CH, CH);
}

// round 11
// speedup vs baseline: 2.3184x; 2.3184x over previous
#include <cuda_runtime.h>
#include <cuda_fp16.h>
#include <math.h>

#define NH 12
#define NB 4
#define SEQ 1024
#define CH 768
#define HD 64
#define BHD 48   // NB*NH
#define QKVLD 2304
#define LOG2E 1.4426950408889634f

// -------- scratch (no allocs allowed) --------
__device__ float g_qkv[NB * SEQ * 3 * CH];   // (4096, 2304)
__device__ float g_relh[BHD * SEQ * 32];
__device__ float g_relw[BHD * SEQ * 32];
__device__ float g_attn[NB * SEQ * CH];      // (4096, 768)

__device__ __forceinline__ unsigned su32(const void* p) {
    unsigned a;
    asm("{ .reg .u64 t; cvta.to.shared.u64 t, %1; cvt.u32.u64 %0, t; }" : "=r"(a) : "l"(p));
    return a;
}
// pack two floats -> half2 (lo, hi)
__device__ __forceinline__ unsigned f2h2(float lo, float hi) {
    unsigned r;
    asm("cvt.rn.f16x2.f32 %0, %1, %2;" : "=r"(r) : "f"(hi), "f"(lo));
    return r;
}
__device__ __forceinline__ float ex2(float x) {
    float y; asm("ex2.approx.ftz.f32 %0, %1;" : "=f"(y) : "f"(x)); return y;
}
__device__ __forceinline__ void ldm4(unsigned* r, unsigned a) {
    asm volatile("ldmatrix.sync.aligned.m8n8.x4.shared.b16 {%0,%1,%2,%3}, [%4];"
        : "=r"(r[0]), "=r"(r[1]), "=r"(r[2]), "=r"(r[3]) : "r"(a));
}
__device__ __forceinline__ void ldm4t(unsigned* r, unsigned a) {
    asm volatile("ldmatrix.sync.aligned.m8n8.x4.trans.shared.b16 {%0,%1,%2,%3}, [%4];"
        : "=r"(r[0]), "=r"(r[1]), "=r"(r[2]), "=r"(r[3]) : "r"(a));
}
// D += A*B, m16n8k16 fp16 in / fp32 accum.
__device__ __forceinline__ void mma_f16(float* d, const unsigned* a, const unsigned* b) {
    asm volatile(
        "mma.sync.aligned.m16n8k16.row.col.f32.f16.f16.f32 "
        "{%0,%1,%2,%3}, {%4,%5,%6,%7}, {%8,%9}, {%0,%1,%2,%3};\n"
        : "+f"(d[0]), "+f"(d[1]), "+f"(d[2]), "+f"(d[3])
        : "r"(a[0]), "r"(a[1]), "r"(a[2]), "r"(a[3]), "r"(b[0]), "r"(b[1]));
}

// ============================================================
// FP16 GEMM: C[M,N] = A[M,K] @ B[K,N] (+bias).
// Block 128x128, BK=32, 256 threads, 8 warps (2m x 4n), warp tile 64x32.
// A smem: [m][kpair b32], stride 20, a-frags via ldmatrix.x4.
// B smem: k-pair-gathered [kp][n] half2, stride 136, scalar b-frag LDS.
// Single-buffered (R7 structure).
// ============================================================
#define ALDG 20
#define BLDG 136

template <bool BIAS>
__global__ __launch_bounds__(256) void gemm_f16(
    const float* __restrict__ A, const float* __restrict__ B,
    const float* __restrict__ bias, float* __restrict__ Cm,
    int M, int N, int K) {
    __shared__ __align__(16) unsigned As[128 * ALDG];
    __shared__ __align__(16) unsigned Bs[16 * BLDG];

    int tid = threadIdx.x;
    int lane = tid & 31, w = tid >> 5;
    int g = lane >> 2, t4 = lane & 3;
    int wm = (w & 1) * 64, wn = (w >> 1) * 32;
    int bm = blockIdx.y * 128, bn = blockIdx.x * 128;

    const int a_r = tid >> 3, a_k = (tid & 7) * 4;   // A: 32 rows x 8 float4 (x4 ii)
    const int b_kp = tid >> 5;                       // kp = b_kp + 8h
    const int b_n = (tid & 31) * 4;

    const unsigned aBase = su32(As);
    const int arow_l = (lane & 7) + 8 * ((lane >> 3) & 1);
    const int acol_l = 4 * (lane >> 4);

    float acc[4][4][4];
#pragma unroll
    for (int i = 0; i < 4; i++)
#pragma unroll
        for (int j = 0; j < 4; j++)
#pragma unroll
            for (int r = 0; r < 4; r++) acc[i][j][r] = 0.f;

    float4 areg[4], breg0[2], breg1[2];
    auto loadg = [&](int k0) {
#pragma unroll
        for (int ii = 0; ii < 4; ii++)
            areg[ii] = *(const float4*)&A[(size_t)(bm + a_r + 32 * ii) * K + k0 + a_k];
#pragma unroll
        for (int h = 0; h < 2; h++) {
            int kk = k0 + 2 * (b_kp + 8 * h);
            breg0[h] = *(const float4*)&B[(size_t)kk * N + bn + b_n];
            breg1[h] = *(const float4*)&B[(size_t)(kk + 1) * N + bn + b_n];
        }
    };
    auto stores = [&]() {
#pragma unroll
        for (int ii = 0; ii < 4; ii++) {
            uint2 u;
            u.x = f2h2(areg[ii].x, areg[ii].y);
            u.y = f2h2(areg[ii].z, areg[ii].w);
            *(uint2*)&As[(a_r + 32 * ii) * ALDG + (a_k >> 1)] = u;
        }
#pragma unroll
        for (int h = 0; h < 2; h++) {
            uint4 v;
            v.x = f2h2(breg0[h].x, breg1[h].x);
            v.y = f2h2(breg0[h].y, breg1[h].y);
            v.z = f2h2(breg0[h].z, breg1[h].z);
            v.w = f2h2(breg0[h].w, breg1[h].w);
            *(uint4*)&Bs[(b_kp + 8 * h) * BLDG + b_n] = v;
        }
    };

    const int KC = K >> 5;
    loadg(0);
    for (int kc = 0; kc < KC; kc++) {
        __syncthreads();
        stores();
        __syncthreads();
        if (kc + 1 < KC) loadg((kc + 1) * 32);
#pragma unroll
        for (int c = 0; c < 2; c++) {
            unsigned af[4][4], bf[4][2];
#pragma unroll
            for (int i = 0; i < 4; i++)
                ldm4(af[i], aBase + ((wm + 16 * i + arow_l) * ALDG + 8 * c + acol_l) * 4);
#pragma unroll
            for (int j = 0; j < 4; j++) {
                bf[j][0] = Bs[(8 * c + t4) * BLDG + wn + 8 * j + g];
                bf[j][1] = Bs[(8 * c + t4 + 4) * BLDG + wn + 8 * j + g];
            }
#pragma unroll
            for (int i = 0; i < 4; i++)
#pragma unroll
                for (int j = 0; j < 4; j++)
                    mma_f16(acc[i][j], af[i], bf[j]);
        }
    }

#pragma unroll
    for (int i = 0; i < 4; i++)
#pragma unroll
        for (int j = 0; j < 4; j++) {
            int row = bm + wm + 16 * i + g;
            int col = bn + wn + 8 * j + 2 * t4;
            float2 v0 = make_float2(acc[i][j][0], acc[i][j][1]);
            float2 v1 = make_float2(acc[i][j][2], acc[i][j][3]);
            if (BIAS) {
                float2 bb = *(const float2*)&bias[col];
                v0.x += bb.x; v0.y += bb.y; v1.x += bb.x; v1.y += bb.y;
            }
            *(float2*)&Cm[(size_t)row * N + col] = v0;
            *(float2*)&Cm[(size_t)(row + 8) * N + col] = v1;
        }
}

// ============================================================
// Relative position bias (unchanged).
// ============================================================
__global__ __launch_bounds__(256) void relpos_kernel(
    const float* __restrict__ rph, const float* __restrict__ rpw) {
    __shared__ float Rh[63 * 68], Rw[63 * 68];
    int tid = threadIdx.x;
    int qc = blockIdx.x, bh = blockIdx.y;

    for (int idx = tid; idx < 63 * 64; idx += 256) {
        int row = idx >> 6, d = idx & 63;
        Rh[row * 68 + d] = rph[idx];
        Rw[row * 68 + d] = rpw[idx];
    }
    __syncthreads();

    int ql = tid >> 1, half = tid & 1;
    int q = qc * 128 + ql;
    int b = bh / NH, head = bh % NH;
    int pc = half ? (q & 31) : (q >> 5);
    const float* qptr = &g_qkv[(size_t)(b * SEQ + q) * QKVLD + head * HD];
    const float* T = half ? Rw : Rh;

    float acc[32];
#pragma unroll
    for (int o = 0; o < 32; o++) acc[o] = 0.f;

    for (int d0 = 0; d0 < 64; d0 += 8) {
        float4 v0 = *(const float4*)&qptr[d0];
        float4 v1 = *(const float4*)&qptr[d0 + 4];
        float qd[8] = {v0.x, v0.y, v0.z, v0.w, v1.x, v1.y, v1.z, v1.w};
#pragma unroll
        for (int dd = 0; dd < 8; dd++) {
            float qv = qd[dd];
            const float* Tp = &T[(pc + 31) * 68 + d0 + dd];
#pragma unroll
            for (int o = 0; o < 32; o++)
                acc[o] = fmaf(qv, Tp[-o * 68], acc[o]);
        }
    }
    float* dst = half ? &g_relw[((size_t)bh * SEQ + q) * 32]
                      : &g_relh[((size_t)bh * SEQ + q) * 32];
#pragma unroll
    for (int o = 0; o < 32; o++) dst[o] = acc[o];
}

// ============================================================
// Flash attention fp16 MMA, warp-local softmax. Bq=128, Bk=64,
// 256 thr, 8 warps; warp owns 16 q-rows x full 64 kv cols.
// K/V smem row-major [key][dpair b32] stride 36, frags via ldmatrix.
// P per-warp [16][36], a-frags via ldmatrix. R7 single-buffer loop.
// ============================================================
#define BQ 128
#define KVLD 36
#define PLD 36
#define LDH 33
#define ATTN_SMEM ((2 * 64 * KVLD + 8 * 16 * PLD + BQ * LDH) * 4)

__global__ __launch_bounds__(256, 2) void attn_mma() {
    extern __shared__ __align__(16) unsigned smu[];
    unsigned* Ks = smu;                     // [64][KVLD]
    unsigned* Vs = Ks + 64 * KVLD;          // [64][KVLD]
    unsigned* Pw = Vs + 64 * KVLD;          // 8 x [16][PLD]
    float* Bhs = (float*)(Pw + 8 * 16 * PLD);  // [BQ][LDH] relh * log2e

    int tid = threadIdx.x;
    int lane = tid & 31, w = tid >> 5;
    int g = lane >> 2, t4 = lane & 3;

    int bh = blockIdx.y, qbase = blockIdx.x * BQ;
    int b = bh / NH, head = bh % NH;
    const float* base = &g_qkv[(size_t)b * SEQ * QKVLD + head * HD];

    // stage relh (log2 domain)
    {
        const float* gh = &g_relh[((size_t)bh * SEQ + qbase) * 32];
        for (int idx = tid; idx < BQ * 32; idx += 256) {
            int r = idx >> 5, c = idx & 31;
            Bhs[r * LDH + c] = LOG2E * gh[r * 32 + c];
        }
    }

    int qr0 = w * 16 + g;      // local q row (a0/a2)
    int qr1 = qr0 + 8;         // (a1/a3)

    // Q fragments in registers: 4 k16 steps over d=64
    unsigned qa[4][4];
    {
        const float* qp0 = base + (size_t)(qbase + qr0) * QKVLD;
        const float* qp1 = base + (size_t)(qbase + qr1) * QKVLD;
#pragma unroll
        for (int c = 0; c < 4; c++) {
            qa[c][0] = f2h2(qp0[16 * c + 2 * t4], qp0[16 * c + 2 * t4 + 1]);
            qa[c][1] = f2h2(qp1[16 * c + 2 * t4], qp1[16 * c + 2 * t4 + 1]);
            qa[c][2] = f2h2(qp0[16 * c + 2 * t4 + 8], qp0[16 * c + 2 * t4 + 9]);
            qa[c][3] = f2h2(qp1[16 * c + 2 * t4 + 8], qp1[16 * c + 2 * t4 + 9]);
        }
    }
    // relw registers, log2 domain
    float rw0[8], rw1[8];
    {
        const float* p0 = &g_relw[((size_t)bh * SEQ + qbase + qr0) * 32];
        const float* p1 = &g_relw[((size_t)bh * SEQ + qbase + qr1) * 32];
#pragma unroll
        for (int m = 0; m < 4; m++) {
            rw0[2 * m]     = LOG2E * p0[8 * m + 2 * t4];
            rw0[2 * m + 1] = LOG2E * p0[8 * m + 2 * t4 + 1];
            rw1[2 * m]     = LOG2E * p1[8 * m + 2 * t4];
            rw1[2 * m + 1] = LOG2E * p1[8 * m + 2 * t4 + 1];
        }
    }

    float m0 = -1e30f, m1 = -1e30f, l0 = 0.f, l1 = 0.f;
    float oacc[8][4];
#pragma unroll
    for (int nb = 0; nb < 8; nb++)
#pragma unroll
        for (int r = 0; r < 4; r++) oacc[nb][r] = 0.f;

    const int r_ = tid >> 4, d4 = (tid & 15) * 4;
    unsigned* Pme = Pw + w * 16 * PLD;
    const unsigned kBase = su32(Ks), vBase = su32(Vs), pBase = su32(Pme);
    const float sc = 0.125f * LOG2E;

    // ldmatrix lane geometry
    const int l7 = lane & 7, le = (lane >> 3) & 1, lh = lane >> 4;
    // K b-frag (non-trans on [key][dp]): row = key, col = dp
    const int krow_l = 8 * lh + l7;          // + 16*nbp
    const int kcol_l = 4 * le;               // + 8*c
    // V b-frag (trans on [key][dp]): row = key = 16c + ..., col = d-block
    const int vrow_l = l7 + 8 * le;          // + 16*c
    const int vcol_l = 4 * lh;               // + 8*nbp
    // P a-frag (non-trans on [m][kp]): row = m, col = kp
    const int prow_l = l7 + 8 * le;
    const int pcol_l = 4 * lh;               // + 8*c

    for (int kt = 0; kt < 16; kt++) {
        __syncthreads();
        // fill K/V tiles: [key][dpair] fp16
#pragma unroll
        for (int ii = 0; ii < 4; ii++) {
            int row = r_ + 16 * ii;
            const float* kp = base + (size_t)(kt * 64 + row) * QKVLD + CH + d4;
            float4 kv = *(const float4*)kp;
            uint2 ku;
            ku.x = f2h2(kv.x, kv.y); ku.y = f2h2(kv.z, kv.w);
            *(uint2*)&Ks[row * KVLD + (d4 >> 1)] = ku;
            float4 vv = *(const float4*)(kp + CH);
            uint2 vu;
            vu.x = f2h2(vv.x, vv.y); vu.y = f2h2(vv.z, vv.w);
            *(uint2*)&Vs[row * KVLD + (d4 >> 1)] = vu;
        }
        __syncthreads();

        // S = Q K^T over the warp's 16 rows x 64 cols
        float sacc[8][4];
#pragma unroll
        for (int nb = 0; nb < 8; nb++)
#pragma unroll
            for (int r = 0; r < 4; r++) sacc[nb][r] = 0.f;
#pragma unroll
        for (int c = 0; c < 4; c++) {
#pragma unroll
            for (int nbp = 0; nbp < 4; nbp++) {
                unsigned kb[4];
                ldm4(kb, kBase + ((16 * nbp + krow_l) * KVLD + 8 * c + kcol_l) * 4);
                mma_f16(sacc[2 * nbp], qa[c], kb);
                mma_f16(sacc[2 * nbp + 1], qa[c], kb + 2);
            }
        }

        // bias + warp-local online softmax (log2 domain)
        float rh0a = Bhs[qr0 * LDH + 2 * kt], rh0b = Bhs[qr0 * LDH + 2 * kt + 1];
        float rh1a = Bhs[qr1 * LDH + 2 * kt], rh1b = Bhs[qr1 * LDH + 2 * kt + 1];
        float mn0 = m0, mn1 = m1;
#pragma unroll
        for (int nb = 0; nb < 8; nb++) {
            float bh0 = nb < 4 ? rh0a : rh0b;
            float bh1 = nb < 4 ? rh1a : rh1b;
            int mi = nb & 3;
            sacc[nb][0] = fmaf(sc, sacc[nb][0], bh0 + rw0[2 * mi]);
            sacc[nb][1] = fmaf(sc, sacc[nb][1], bh0 + rw0[2 * mi + 1]);
            sacc[nb][2] = fmaf(sc, sacc[nb][2], bh1 + rw1[2 * mi]);
            sacc[nb][3] = fmaf(sc, sacc[nb][3], bh1 + rw1[2 * mi + 1]);
            mn0 = fmaxf(mn0, fmaxf(sacc[nb][0], sacc[nb][1]));
            mn1 = fmaxf(mn1, fmaxf(sacc[nb][2], sacc[nb][3]));
        }
        mn0 = fmaxf(mn0, __shfl_xor_sync(0xffffffffu, mn0, 1));
        mn0 = fmaxf(mn0, __shfl_xor_sync(0xffffffffu, mn0, 2));
        mn1 = fmaxf(mn1, __shfl_xor_sync(0xffffffffu, mn1, 1));
        mn1 = fmaxf(mn1, __shfl_xor_sync(0xffffffffu, mn1, 2));
        float cr0 = ex2(m0 - mn0), cr1 = ex2(m1 - mn1);
        m0 = mn0; m1 = mn1;
        float s0 = 0.f, s1 = 0.f;
#pragma unroll
        for (int nb = 0; nb < 8; nb++) {
            float p0 = ex2(sacc[nb][0] - mn0);
            float p1 = ex2(sacc[nb][1] - mn0);
            float p2 = ex2(sacc[nb][2] - mn1);
            float p3 = ex2(sacc[nb][3] - mn1);
            s0 += p0 + p1; s1 += p2 + p3;
            // P[m][kpair]: kp = 4nb + t4; bank = 4g + t4 (conflict-free)
            Pme[g * PLD + 4 * nb + t4] = f2h2(p0, p1);
            Pme[(g + 8) * PLD + 4 * nb + t4] = f2h2(p2, p3);
        }
        s0 += __shfl_xor_sync(0xffffffffu, s0, 1);
        s0 += __shfl_xor_sync(0xffffffffu, s0, 2);
        s1 += __shfl_xor_sync(0xffffffffu, s1, 1);
        s1 += __shfl_xor_sync(0xffffffffu, s1, 2);
        l0 = l0 * cr0 + s0;
        l1 = l1 * cr1 + s1;
#pragma unroll
        for (int nb = 0; nb < 8; nb++) {
            oacc[nb][0] *= cr0; oacc[nb][1] *= cr0;
            oacc[nb][2] *= cr1; oacc[nb][3] *= cr1;
        }
        __syncwarp();

        // O += P @ V
#pragma unroll
        for (int c = 0; c < 4; c++) {
            unsigned pa[4];
            ldm4(pa, pBase + (prow_l * PLD + 8 * c + pcol_l) * 4);
#pragma unroll
            for (int nbp = 0; nbp < 4; nbp++) {
                unsigned vb[4];
                ldm4t(vb, vBase + ((16 * c + vrow_l) * KVLD + 8 * nbp + vcol_l) * 4);
                mma_f16(oacc[2 * nbp], pa, vb);
                mma_f16(oacc[2 * nbp + 1], pa, vb + 2);
            }
        }
    }

    // normalize + write (B,S,C) layout
    float inv0 = 1.f / l0, inv1 = 1.f / l1;
    float* op0 = &g_attn[(size_t)(b * SEQ + qbase + qr0) * CH + head * HD + 2 * t4];
    float* op1 = &g_attn[(size_t)(b * SEQ + qbase + qr1) * CH + head * HD + 2 * t4];
#pragma unroll
    for (int nb = 0; nb < 8; nb++) {
        *(float2*)&op0[8 * nb] = make_float2(oacc[nb][0] * inv0, oacc[nb][1] * inv0);
        *(float2*)&op1[8 * nb] = make_float2(oacc[nb][2] * inv1, oacc[nb][3] * inv1);
    }
}

// ============================================================
extern "C" void kernel_launch(void* const* d_in, const int* in_sizes, int n_in,
                              void* d_out, int out_size) {
    const float* x     = (const float*)d_in[0];
    const float* Wqkv  = (const float*)d_in[1];
    const float* Wproj = (const float*)d_in[2];
    const float* bproj = (const float*)d_in[3];
    const float* rph   = (const float*)d_in[4];
    const float* rpw   = (const float*)d_in[5];
    float* out = (float*)d_out;

    float* qkv;  cudaGetSymbolAddress((void**)&qkv,  g_qkv);
    float* attn; cudaGetSymbolAddress((void**)&attn, g_attn);

    cudaFuncSetAttribute(attn_mma, cudaFuncAttributeMaxDynamicSharedMemorySize, ATTN_SMEM);

    // 1) QKV projection: (4096 x 2304) = (4096 x 768) @ (768 x 2304)
    gemm_f16<false><<<dim3(QKVLD / 128, (NB * SEQ) / 128), 256>>>(
        x, Wqkv, nullptr, qkv, NB * SEQ, QKVLD, CH);

    // 2) decomposed relative position bias
    relpos_kernel<<<dim3(8, BHD), 256>>>(rph, rpw);

    // 3) attention (fp16 mma + ldmatrix, warp-local online softmax)
    attn_mma<<<dim3(SEQ / BQ, BHD), 256, ATTN_SMEM>>>();

    // 4) out projection + bias: (4096 x 768) = (4096 x 768) @ (768 x 768) + b
    gemm_f16<true><<<dim3(CH / 128, (NB * SEQ) / 128), 256>>>(
        attn, Wproj, bproj, out, NB * SEQ, CH, CH);
}

// round 12
// speedup vs baseline: 2.6593x; 1.1470x over previous
#include <cuda_runtime.h>
#include <cuda_fp16.h>
#include <math.h>

#define NH 12
#define NB 4
#define SEQ 1024
#define CH 768
#define HD 64
#define BHD 48   // NB*NH
#define QKVLD 2304
#define LOG2E 1.4426950408889634f

// -------- scratch (no allocs allowed) --------
__device__ float g_qkv[NB * SEQ * 3 * CH];     // f32 qkv (only Q region used, by relpos)
__device__ __half g_qkvh[NB * SEQ * 3 * CH];   // fp16 qkv (attention)
__device__ __half g_attnh[NB * SEQ * CH];      // fp16 attention output
__device__ __half g_xh[NB * SEQ * CH];         // fp16 x
__device__ __half g_wqkvh[CH * 3 * CH];        // fp16 Wqkv
__device__ __half g_wprojh[CH * CH];           // fp16 Wproj
__device__ float g_relh[BHD * SEQ * 32];
__device__ float g_relw[BHD * SEQ * 32];

__device__ __forceinline__ unsigned su32(const void* p) {
    unsigned a;
    asm("{ .reg .u64 t; cvta.to.shared.u64 t, %1; cvt.u32.u64 %0, t; }" : "=r"(a) : "l"(p));
    return a;
}
__device__ __forceinline__ unsigned f2h2(float lo, float hi) {
    unsigned r;
    asm("cvt.rn.f16x2.f32 %0, %1, %2;" : "=r"(r) : "f"(hi), "f"(lo));
    return r;
}
__device__ __forceinline__ float ex2(float x) {
    float y; asm("ex2.approx.ftz.f32 %0, %1;" : "=f"(y) : "f"(x)); return y;
}
__device__ __forceinline__ void ldm4(unsigned* r, unsigned a) {
    asm volatile("ldmatrix.sync.aligned.m8n8.x4.shared.b16 {%0,%1,%2,%3}, [%4];"
        : "=r"(r[0]), "=r"(r[1]), "=r"(r[2]), "=r"(r[3]) : "r"(a));
}
__device__ __forceinline__ void ldm4t(unsigned* r, unsigned a) {
    asm volatile("ldmatrix.sync.aligned.m8n8.x4.trans.shared.b16 {%0,%1,%2,%3}, [%4];"
        : "=r"(r[0]), "=r"(r[1]), "=r"(r[2]), "=r"(r[3]) : "r"(a));
}
__device__ __forceinline__ void mma_f16(float* d, const unsigned* a, const unsigned* b) {
    asm volatile(
        "mma.sync.aligned.m16n8k16.row.col.f32.f16.f16.f32 "
        "{%0,%1,%2,%3}, {%4,%5,%6,%7}, {%8,%9}, {%0,%1,%2,%3};\n"
        : "+f"(d[0]), "+f"(d[1]), "+f"(d[2]), "+f"(d[3])
        : "r"(a[0]), "r"(a[1]), "r"(a[2]), "r"(a[3]), "r"(b[0]), "r"(b[1]));
}
__device__ __forceinline__ void cpa16(unsigned dst, const void* src) {
    asm volatile("cp.async.cg.shared.global [%0], [%1], 16;\n" :: "r"(dst), "l"(src));
}
#define CP_COMMIT() asm volatile("cp.async.commit_group;\n")
#define CP_WAIT1() asm volatile("cp.async.wait_group 1;\n")

// ============================================================
// f32 -> f16 conversion (pairs)
// ============================================================
__global__ void f2h_kernel(const float* __restrict__ s, __half* __restrict__ d, int n2) {
    int i = blockIdx.x * 256 + threadIdx.x;
    if (i < n2) {
        float2 v = ((const float2*)s)[i];
        ((unsigned*)d)[i] = f2h2(v.x, v.y);
    }
}

// ============================================================
// FP16 GEMM, cp.async 3-stage pipeline.
// C[M,N] = A[M,K]@B[K,N]. Block 128x128, BK=32, 256 thr, 8 warps (2m x 4n).
// A smem rows 80B (40 halves), B smem rows 272B (136 halves): conflict-free
// ldmatrix without swizzle (5r mod 8 / 17r mod 8 bijective).
// MODE 1: f32 out + bias (out-proj). MODE 2: f16 out always + f32 iff bn<768 (QKV).
// ============================================================
#define G_ASTAGE 10240
#define G_BSTAGE 8704
#define GEMM_SMEM (3 * (G_ASTAGE + G_BSTAGE))

template <int MODE>
__global__ __launch_bounds__(256) void gemm_h(
    const __half* __restrict__ A, const __half* __restrict__ B,
    const float* __restrict__ bias, float* __restrict__ Cf, __half* __restrict__ Ch,
    int M, int N, int K) {
    extern __shared__ __align__(16) char gsm[];
    const unsigned sb = su32(gsm);

    int tid = threadIdx.x;
    int lane = tid & 31, w = tid >> 5;
    int g = lane >> 2, t4 = lane & 3;
    int wm = (w & 1) * 64, wn = (w >> 1) * 32;
    int bm = blockIdx.y * 128, bn = blockIdx.x * 128;

    // cp.async mappings
    const int a_row = tid >> 1, a_g = (tid & 1) * 2;   // 2 granules: a_g, a_g+1
    const int b_row = tid >> 4, b_g = tid & 15;        // rows b_row, b_row+16
    const __half* aSrc = A + (size_t)(bm + a_row) * K + 8 * a_g;
    const __half* bSrc = B + (size_t)b_row * N + bn + 8 * b_g;

    // ldmatrix lane geometry
    const int rl = (lane & 7) + 8 * ((lane >> 3) & 1);
    const int gl = lane >> 4;

    float acc[4][4][4];
#pragma unroll
    for (int i = 0; i < 4; i++)
#pragma unroll
        for (int j = 0; j < 4; j++)
#pragma unroll
            for (int r = 0; r < 4; r++) acc[i][j][r] = 0.f;

    auto issue = [&](int kc) {
        int s = kc % 3, k0 = kc * 32;
        unsigned ad = sb + s * G_ASTAGE + a_row * 80 + a_g * 16;
        const __half* ap = aSrc + k0;
        cpa16(ad, ap);
        cpa16(ad + 16, ap + 8);
        unsigned bd = sb + 3 * G_ASTAGE + s * G_BSTAGE + b_row * 272 + b_g * 16;
        const __half* bp = bSrc + (size_t)k0 * N;
        cpa16(bd, bp);
        cpa16(bd + 16 * 272, bp + (size_t)16 * N);
    };

    issue(0); CP_COMMIT();
    issue(1); CP_COMMIT();

    const int KC = K >> 5;
    for (int kc = 0; kc < KC; kc++) {
        CP_WAIT1();
        __syncthreads();
        if (kc + 2 < KC) issue(kc + 2);
        CP_COMMIT();

        int s = kc % 3;
        unsigned aB = sb + s * G_ASTAGE;
        unsigned bB = sb + 3 * G_ASTAGE + s * G_BSTAGE;
#pragma unroll
        for (int c = 0; c < 2; c++) {
            unsigned af[4][4], bf[4][2];
#pragma unroll
            for (int i = 0; i < 4; i++)
                ldm4(af[i], aB + (wm + 16 * i + rl) * 80 + (2 * c + gl) * 16);
#pragma unroll
            for (int jp = 0; jp < 2; jp++) {
                unsigned r[4];
                ldm4t(r, bB + (16 * c + rl) * 272 + ((wn >> 3) + 2 * jp + gl) * 16);
                bf[2 * jp][0] = r[0]; bf[2 * jp][1] = r[1];
                bf[2 * jp + 1][0] = r[2]; bf[2 * jp + 1][1] = r[3];
            }
#pragma unroll
            for (int i = 0; i < 4; i++)
#pragma unroll
                for (int j = 0; j < 4; j++)
                    mma_f16(acc[i][j], af[i], bf[j]);
        }
    }

#pragma unroll
    for (int i = 0; i < 4; i++)
#pragma unroll
        for (int j = 0; j < 4; j++) {
            int row = bm + wm + 16 * i + g;
            int col = bn + wn + 8 * j + 2 * t4;
            float2 v0 = make_float2(acc[i][j][0], acc[i][j][1]);
            float2 v1 = make_float2(acc[i][j][2], acc[i][j][3]);
            if (MODE == 1) {
                float2 bb = *(const float2*)&bias[col];
                v0.x += bb.x; v0.y += bb.y; v1.x += bb.x; v1.y += bb.y;
                *(float2*)&Cf[(size_t)row * N + col] = v0;
                *(float2*)&Cf[(size_t)(row + 8) * N + col] = v1;
            } else {
                *(unsigned*)&Ch[(size_t)row * N + col] = f2h2(v0.x, v0.y);
                *(unsigned*)&Ch[(size_t)(row + 8) * N + col] = f2h2(v1.x, v1.y);
                if (bn < CH) {   // Q region also in f32 for relpos
                    *(float2*)&Cf[(size_t)row * N + col] = v0;
                    *(float2*)&Cf[(size_t)(row + 8) * N + col] = v1;
                }
            }
        }
}

// ============================================================
// Relative position bias (unchanged; reads f32 Q region of g_qkv).
// ============================================================
__global__ __launch_bounds__(256) void relpos_kernel(
    const float* __restrict__ rph, const float* __restrict__ rpw) {
    __shared__ float Rh[63 * 68], Rw[63 * 68];
    int tid = threadIdx.x;
    int qc = blockIdx.x, bh = blockIdx.y;

    for (int idx = tid; idx < 63 * 64; idx += 256) {
        int row = idx >> 6, d = idx & 63;
        Rh[row * 68 + d] = rph[idx];
        Rw[row * 68 + d] = rpw[idx];
    }
    __syncthreads();

    int ql = tid >> 1, half = tid & 1;
    int q = qc * 128 + ql;
    int b = bh / NH, head = bh % NH;
    int pc = half ? (q & 31) : (q >> 5);
    const float* qptr = &g_qkv[(size_t)(b * SEQ + q) * QKVLD + head * HD];
    const float* T = half ? Rw : Rh;

    float acc[32];
#pragma unroll
    for (int o = 0; o < 32; o++) acc[o] = 0.f;

    for (int d0 = 0; d0 < 64; d0 += 8) {
        float4 v0 = *(const float4*)&qptr[d0];
        float4 v1 = *(const float4*)&qptr[d0 + 4];
        float qd[8] = {v0.x, v0.y, v0.z, v0.w, v1.x, v1.y, v1.z, v1.w};
#pragma unroll
        for (int dd = 0; dd < 8; dd++) {
            float qv = qd[dd];
            const float* Tp = &T[(pc + 31) * 68 + d0 + dd];
#pragma unroll
            for (int o = 0; o < 32; o++)
                acc[o] = fmaf(qv, Tp[-o * 68], acc[o]);
        }
    }
    float* dst = half ? &g_relw[((size_t)bh * SEQ + q) * 32]
                      : &g_relh[((size_t)bh * SEQ + q) * 32];
#pragma unroll
    for (int o = 0; o < 32; o++) dst[o] = acc[o];
}

// ============================================================
// Flash attention, fp16 inputs via cp.async 2-stage K/V double buffer.
// Bq=128, Bk=64, 256 thr, 8 warps; warp owns 16 q-rows x 64 kv cols.
// K/V smem rows 144B (72 halves): conflict-free ldmatrix, no swizzle.
// Output written fp16 to g_attnh.
// ============================================================
#define BQ 128
#define PLD 36
#define LDH 33
#define KV_STG 9216                    // bytes per K (or V) stage
#define AT_POFF (4 * KV_STG)           // 36864: P region
#define AT_BOFF (AT_POFF + 8 * 16 * PLD * 4)  // Bhs region
#define ATTN_SMEM (AT_BOFF + BQ * LDH * 4)

__global__ __launch_bounds__(256, 2) void attn_mma() {
    extern __shared__ __align__(16) char sm[];
    const unsigned sb = su32(sm);
    float* Bhs = (float*)(sm + AT_BOFF);

    int tid = threadIdx.x;
    int lane = tid & 31, w = tid >> 5;
    int g = lane >> 2, t4 = lane & 3;

    int bh = blockIdx.y, qbase = blockIdx.x * BQ;
    int b = bh / NH, head = bh % NH;
    const __half* baseh = g_qkvh + (size_t)b * SEQ * QKVLD + head * HD;

    // stage relh (log2 domain)
    {
        const float* gh = &g_relh[((size_t)bh * SEQ + qbase) * 32];
        for (int idx = tid; idx < BQ * 32; idx += 256) {
            int r = idx >> 5, c = idx & 31;
            Bhs[r * LDH + c] = LOG2E * gh[r * 32 + c];
        }
    }

    int qr0 = w * 16 + g;
    int qr1 = qr0 + 8;

    // Q fragments: direct fp16 loads
    unsigned qa[4][4];
    {
        const __half* qp0 = baseh + (size_t)(qbase + qr0) * QKVLD;
        const __half* qp1 = baseh + (size_t)(qbase + qr1) * QKVLD;
#pragma unroll
        for (int c = 0; c < 4; c++) {
            qa[c][0] = *(const unsigned*)&qp0[16 * c + 2 * t4];
            qa[c][1] = *(const unsigned*)&qp1[16 * c + 2 * t4];
            qa[c][2] = *(const unsigned*)&qp0[16 * c + 2 * t4 + 8];
            qa[c][3] = *(const unsigned*)&qp1[16 * c + 2 * t4 + 8];
        }
    }
    // relw registers, log2 domain
    float rw0[8], rw1[8];
    {
        const float* p0 = &g_relw[((size_t)bh * SEQ + qbase + qr0) * 32];
        const float* p1 = &g_relw[((size_t)bh * SEQ + qbase + qr1) * 32];
#pragma unroll
        for (int m = 0; m < 4; m++) {
            rw0[2 * m]     = LOG2E * p0[8 * m + 2 * t4];
            rw0[2 * m + 1] = LOG2E * p0[8 * m + 2 * t4 + 1];
            rw1[2 * m]     = LOG2E * p1[8 * m + 2 * t4];
            rw1[2 * m + 1] = LOG2E * p1[8 * m + 2 * t4 + 1];
        }
    }

    float m0 = -1e30f, m1 = -1e30f, l0 = 0.f, l1 = 0.f;
    float oacc[8][4];
#pragma unroll
    for (int nb = 0; nb < 8; nb++)
#pragma unroll
        for (int r = 0; r < 4; r++) oacc[nb][r] = 0.f;

    // cp.async K/V mapping: thread -> row tid>>2, granules 2(tid&3), +1
    const int kv_r = tid >> 2, kv_g = (tid & 3) * 2;
    const __half* kvSrc = baseh + (size_t)kv_r * QKVLD + CH + 8 * kv_g;

    auto issue = [&](int kt) {
        int s = kt & 1;
        const __half* kp = kvSrc + (size_t)(kt * 64) * QKVLD;
        unsigned kd = sb + s * KV_STG + kv_r * 144 + kv_g * 16;
        cpa16(kd, kp);
        cpa16(kd + 16, kp + 8);
        const __half* vp = kp + CH;
        unsigned vd = kd + 2 * KV_STG;
        cpa16(vd, vp);
        cpa16(vd + 16, vp + 8);
    };

    unsigned* Pme = (unsigned*)(sm + AT_POFF) + w * 16 * PLD;
    const unsigned pBase = su32(Pme);
    const float sc = 0.125f * LOG2E;

    // ldmatrix lane geometry
    const int l7 = lane & 7, le = (lane >> 3) & 1, lh = lane >> 4;
    const int krow_l = 8 * lh + l7;
    const int vrow_l = l7 + 8 * le;
    const int prow_l = l7 + 8 * le;

    issue(0); CP_COMMIT();

    for (int kt = 0; kt < 16; kt++) {
        __syncthreads();                 // buffer (kt+1)&1 free for reuse
        if (kt + 1 < 16) issue(kt + 1);
        CP_COMMIT();
        CP_WAIT1();
        __syncthreads();

        const unsigned kB = sb + (kt & 1) * KV_STG;
        const unsigned vB = kB + 2 * KV_STG;

        // S = Q K^T
        float sacc[8][4];
#pragma unroll
        for (int nb = 0; nb < 8; nb++)
#pragma unroll
            for (int r = 0; r < 4; r++) sacc[nb][r] = 0.f;
#pragma unroll
        for (int c = 0; c < 4; c++) {
#pragma unroll
            for (int nbp = 0; nbp < 4; nbp++) {
                unsigned kb[4];
                ldm4(kb, kB + (16 * nbp + krow_l) * 144 + c * 32 + le * 16);
                mma_f16(sacc[2 * nbp], qa[c], kb);
                mma_f16(sacc[2 * nbp + 1], qa[c], kb + 2);
            }
        }

        // bias + warp-local online softmax (log2 domain)
        float rh0a = Bhs[qr0 * LDH + 2 * kt], rh0b = Bhs[qr0 * LDH + 2 * kt + 1];
        float rh1a = Bhs[qr1 * LDH + 2 * kt], rh1b = Bhs[qr1 * LDH + 2 * kt + 1];
        float mn0 = m0, mn1 = m1;
#pragma unroll
        for (int nb = 0; nb < 8; nb++) {
            float bh0 = nb < 4 ? rh0a : rh0b;
            float bh1 = nb < 4 ? rh1a : rh1b;
            int mi = nb & 3;
            sacc[nb][0] = fmaf(sc, sacc[nb][0], bh0 + rw0[2 * mi]);
            sacc[nb][1] = fmaf(sc, sacc[nb][1], bh0 + rw0[2 * mi + 1]);
            sacc[nb][2] = fmaf(sc, sacc[nb][2], bh1 + rw1[2 * mi]);
            sacc[nb][3] = fmaf(sc, sacc[nb][3], bh1 + rw1[2 * mi + 1]);
            mn0 = fmaxf(mn0, fmaxf(sacc[nb][0], sacc[nb][1]));
            mn1 = fmaxf(mn1, fmaxf(sacc[nb][2], sacc[nb][3]));
        }
        mn0 = fmaxf(mn0, __shfl_xor_sync(0xffffffffu, mn0, 1));
        mn0 = fmaxf(mn0, __shfl_xor_sync(0xffffffffu, mn0, 2));
        mn1 = fmaxf(mn1, __shfl_xor_sync(0xffffffffu, mn1, 1));
        mn1 = fmaxf(mn1, __shfl_xor_sync(0xffffffffu, mn1, 2));
        float cr0 = ex2(m0 - mn0), cr1 = ex2(m1 - mn1);
        m0 = mn0; m1 = mn1;
        float s0 = 0.f, s1 = 0.f;
#pragma unroll
        for (int nb = 0; nb < 8; nb++) {
            float p0 = ex2(sacc[nb][0] - mn0);
            float p1 = ex2(sacc[nb][1] - mn0);
            float p2 = ex2(sacc[nb][2] - mn1);
            float p3 = ex2(sacc[nb][3] - mn1);
            s0 += p0 + p1; s1 += p2 + p3;
            Pme[g * PLD + 4 * nb + t4] = f2h2(p0, p1);
            Pme[(g + 8) * PLD + 4 * nb + t4] = f2h2(p2, p3);
        }
        s0 += __shfl_xor_sync(0xffffffffu, s0, 1);
        s0 += __shfl_xor_sync(0xffffffffu, s0, 2);
        s1 += __shfl_xor_sync(0xffffffffu, s1, 1);
        s1 += __shfl_xor_sync(0xffffffffu, s1, 2);
        l0 = l0 * cr0 + s0;
        l1 = l1 * cr1 + s1;
#pragma unroll
        for (int nb = 0; nb < 8; nb++) {
            oacc[nb][0] *= cr0; oacc[nb][1] *= cr0;
            oacc[nb][2] *= cr1; oacc[nb][3] *= cr1;
        }
        __syncwarp();

        // O += P @ V
#pragma unroll
        for (int c = 0; c < 4; c++) {
            unsigned pa[4];
            ldm4(pa, pBase + prow_l * (PLD * 4) + c * 32 + lh * 16);
#pragma unroll
            for (int nbp = 0; nbp < 4; nbp++) {
                unsigned vb[4];
                ldm4t(vb, vB + (16 * c + vrow_l) * 144 + nbp * 32 + lh * 16);
                mma_f16(oacc[2 * nbp], pa, vb);
                mma_f16(oacc[2 * nbp + 1], pa, vb + 2);
            }
        }
    }

    // normalize + write fp16 (B,S,C) layout
    float inv0 = 1.f / l0, inv1 = 1.f / l1;
    __half* op0 = &g_attnh[(size_t)(b * SEQ + qbase + qr0) * CH + head * HD + 2 * t4];
    __half* op1 = &g_attnh[(size_t)(b * SEQ + qbase + qr1) * CH + head * HD + 2 * t4];
#pragma unroll
    for (int nb = 0; nb < 8; nb++) {
        *(unsigned*)&op0[8 * nb] = f2h2(oacc[nb][0] * inv0, oacc[nb][1] * inv0);
        *(unsigned*)&op1[8 * nb] = f2h2(oacc[nb][2] * inv1, oacc[nb][3] * inv1);
    }
}

// ============================================================
extern "C" void kernel_launch(void* const* d_in, const int* in_sizes, int n_in,
                              void* d_out, int out_size) {
    const float* x     = (const float*)d_in[0];
    const float* Wqkv  = (const float*)d_in[1];
    const float* Wproj = (const float*)d_in[2];
    const float* bproj = (const float*)d_in[3];
    const float* rph   = (const float*)d_in[4];
    const float* rpw   = (const float*)d_in[5];
    float* out = (float*)d_out;

    float* qkv;   cudaGetSymbolAddress((void**)&qkv,   g_qkv);
    __half* qkvh; cudaGetSymbolAddress((void**)&qkvh,  g_qkvh);
    __half* attnh; cudaGetSymbolAddress((void**)&attnh, g_attnh);
    __half* xh;   cudaGetSymbolAddress((void**)&xh,    g_xh);
    __half* wqh;  cudaGetSymbolAddress((void**)&wqh,   g_wqkvh);
    __half* wph;  cudaGetSymbolAddress((void**)&wph,   g_wprojh);

    cudaFuncSetAttribute(gemm_h<1>, cudaFuncAttributeMaxDynamicSharedMemorySize, GEMM_SMEM);
    cudaFuncSetAttribute(gemm_h<2>, cudaFuncAttributeMaxDynamicSharedMemorySize, GEMM_SMEM);
    cudaFuncSetAttribute(attn_mma, cudaFuncAttributeMaxDynamicSharedMemorySize, ATTN_SMEM);

    // 0) f32 -> f16 conversions
    {
        int n2 = NB * SEQ * CH / 2;
        f2h_kernel<<<(n2 + 255) / 256, 256>>>(x, xh, n2);
        n2 = CH * 3 * CH / 2;
        f2h_kernel<<<(n2 + 255) / 256, 256>>>(Wqkv, wqh, n2);
        n2 = CH * CH / 2;
        f2h_kernel<<<(n2 + 255) / 256, 256>>>(Wproj, wph, n2);
    }

    // 1) QKV projection: fp16 out (+ f32 Q region for relpos)
    gemm_h<2><<<dim3(QKVLD / 128, (NB * SEQ) / 128), 256, GEMM_SMEM>>>(
        xh, wqh, nullptr, qkv, qkvh, NB * SEQ, QKVLD, CH);

    // 2) decomposed relative position bias
    relpos_kernel<<<dim3(8, BHD), 256>>>(rph, rpw);

    // 3) attention (fp16 mma + cp.async double buffer)
    attn_mma<<<dim3(SEQ / BQ, BHD), 256, ATTN_SMEM>>>();

    // 4) out projection + bias -> f32 output
    gemm_h<1><<<dim3(CH / 128, (NB * SEQ) / 128), 256, GEMM_SMEM>>>(
        attnh, wph, bproj, out, nullptr, NB * SEQ, CH, CH);
}